// round 2
// baseline (speedup 1.0000x reference)
#include <cuda_runtime.h>
#include <cstdint>

#define NB 8
#define NP 2048
#define NCF 1024
#define NCLS 3

// ---------------- scratch (__device__ globals; no allocation allowed) ----------------
__device__ float4 g_pt[NB][NP];                    // sorted (x,y,z,label-bits)
__device__ float  g_L[NB][NP];                     // exact squared-radius threshold
__device__ int    g_sidx[NB][NP];                  // sorted -> original index
__device__ unsigned long long g_mask[NB][NP][32];  // suppression bitmask rows (4MB)
__device__ unsigned char g_keep[NB * NP];          // keep flags by original index

// ---------------- K1: scores, labels, sort by (score desc, idx asc) ----------------
__global__ __launch_bounds__(1024) void k1_sort(const float* __restrict__ centers,
                                                const float* __restrict__ cls,
                                                const float* __restrict__ radius)
{
    __shared__ unsigned long long keys[NP];
    const int b = blockIdx.x;
    const int tid = threadIdx.x;

    for (int p = tid; p < NP; p += 1024) {
        const float* cp = cls + ((size_t)b * NP + p) * NCLS;
        float c0 = cp[0], c1 = cp[1], c2 = cp[2];
        float s = c0;
        if (c1 > s) s = c1;
        if (c2 > s) s = c2;
        unsigned su = __float_as_uint(s);
        unsigned ord = su ^ ((su & 0x80000000u) ? 0xFFFFFFFFu : 0x80000000u);
        // ascending sort of key => score descending, index ascending (argmax tie-break)
        keys[p] = ((unsigned long long)(~ord) << 32) | (unsigned)p;
    }
    __syncthreads();

    // bitonic sort, 2048 elems, 1024 threads
    for (int k = 2; k <= NP; k <<= 1) {
        for (int j = k >> 1; j > 0; j >>= 1) {
            for (int t = tid; t < NP; t += 1024) {
                int ixj = t ^ j;
                if (ixj > t) {
                    unsigned long long a = keys[t], c = keys[ixj];
                    bool up = ((t & k) == 0);
                    if ((a > c) == up) { keys[t] = c; keys[ixj] = a; }
                }
            }
            __syncthreads();
        }
    }

    for (int p = tid; p < NP; p += 1024) {
        int idx = (int)(keys[p] & 0xFFFFFFFFu);
        g_sidx[b][p] = idx;
        const float* cc = centers + ((size_t)b * NP + idx) * 3;
        const float* cp = cls + ((size_t)b * NP + idx) * NCLS;
        float c0 = cp[0], c1 = cp[1], c2 = cp[2];
        int lab = 0; float s = c0;
        if (c1 > s) { s = c1; lab = 1; }
        if (c2 > s) { s = c2; lab = 2; }
        g_pt[b][p] = make_float4(cc[0], cc[1], cc[2], __int_as_float(lab));

        // Exact threshold: RN(sqrt(d2)) < r  <=>  d2 <= L, where
        // L = largest f32 strictly below M = ((pred(r)+r)/2)^2 (real arithmetic).
        float r = radius[lab];
        float L;
        if (!(r > 0.0f)) {
            L = -1.0f;  // dist < r never true
        } else {
            float pr = __uint_as_float(__float_as_uint(r) - 1u);
            double m = 0.5 * ((double)pr + (double)r);
            double M = m * m;
            float f = (float)M;
            if ((double)f < M) L = f;
            else L = __uint_as_float(__float_as_uint(f) - 1u);
        }
        g_L[b][p] = L;
    }
}

// ---------------- K2: build suppression bit-matrix in sorted order ----------------
// grid (16, 8): 16 row-tiles of 128 rows per scene. 128 threads = 4 warps,
// one warp owns 32 consecutive rows (lane = row). Broadcast j-data from shared.
__global__ __launch_bounds__(128) void k2_mask()
{
    __shared__ float4 spt[NP];  // 32KB
    const int b = blockIdx.y;
    const int tid = threadIdx.x;

    for (int k = tid; k < NP; k += 128) spt[k] = g_pt[b][k];
    __syncthreads();

    const int warp = tid >> 5, lane = tid & 31;
    const int wbase = blockIdx.x * 128 + warp * 32;
    const int i = wbase + lane;

    const float4 me = spt[i];
    const int li = __float_as_int(me.w);
    const float Li = g_L[b][i];

    for (int jc = 0; jc < 32; jc++) {
        if (jc * 64 + 63 < wbase) continue;  // all j < i in this word: never read by scan
        unsigned long long bits = 0ull;
        const int jb = jc << 6;
        #pragma unroll 8
        for (int jj = 0; jj < 64; jj++) {
            float4 q = spt[jb + jj];
            float dx = me.x - q.x;
            float dy = me.y - q.y;
            float dz = me.z - q.z;
            // match XLA: (dx*dx + dy*dy) + dz*dz, no FMA contraction
            float d2 = __fadd_rn(__fadd_rn(__fmul_rn(dx, dx), __fmul_rn(dy, dy)),
                                 __fmul_rn(dz, dz));
            bool pr = (__float_as_int(q.w) == li) && (d2 <= Li);
            bits |= ((unsigned long long)pr) << jj;
        }
        g_mask[b][i][jc] = bits;
    }
}

// ---------------- K3: sequential greedy scan, one warp per scene ----------------
#define SCAND 16
__global__ __launch_bounds__(32) void k3_scan(float* __restrict__ out_keep)
{
    __shared__ unsigned long long ring[SCAND][32];
    __shared__ int ssidx[NP];
    const int b = blockIdx.x;
    const int lane = threadIdx.x;

    for (int k = lane; k < NP; k += 32) ssidx[k] = g_sidx[b][k];
    __syncwarp();

    unsigned long long removed = 0ull;  // lane l owns removed word l

    #pragma unroll
    for (int d = 0; d < SCAND; d++) {
        unsigned sa = (unsigned)__cvta_generic_to_shared(&ring[d][lane]);
        const unsigned long long* ga = &g_mask[b][d][lane];
        asm volatile("cp.async.ca.shared.global [%0], [%1], 8;\n" :: "r"(sa), "l"(ga) : "memory");
        asm volatile("cp.async.commit_group;\n" ::: "memory");
    }

    for (int i = 0; i < NP; i++) {
        // one group committed per row; keep <= SCAND-1 pending => row i landed
        asm volatile("cp.async.wait_group %0;\n" :: "n"(SCAND - 1) : "memory");

        int w = i >> 6;
        unsigned long long rw = __shfl_sync(0xFFFFFFFFu, removed, w);
        bool kept = ((rw >> (i & 63)) & 1ull) == 0ull;

        unsigned long long rword = ring[i & (SCAND - 1)][lane];
        if (kept) removed |= rword;

        if (lane == 0) {
            int oi = ssidx[i];
            g_keep[b * NP + oi] = kept ? 1 : 0;
            out_keep[b * NP + oi] = kept ? 1.0f : 0.0f;
        }

        int nxt = i + SCAND;
        if (nxt < NP) {
            unsigned sa = (unsigned)__cvta_generic_to_shared(&ring[i & (SCAND - 1)][lane]);
            const unsigned long long* ga = &g_mask[b][nxt][lane];
            asm volatile("cp.async.ca.shared.global [%0], [%1], 8;\n" :: "r"(sa), "l"(ga) : "memory");
        }
        asm volatile("cp.async.commit_group;\n" ::: "memory");  // empty group ok at tail
    }
}

// ---------------- K4: apply keep mask to all output sections ----------------
// out layout (floats): centers @0 (49152) | features @49152 (16777216) |
//                      cls @16826368 (49152) | keep @16875520 (16384, written by K3)
__global__ __launch_bounds__(256) void k4_apply(const float* __restrict__ centers,
                                                const float* __restrict__ features,
                                                const float* __restrict__ cls,
                                                float* __restrict__ out)
{
    const int NF4 = NB * NP * NCF / 4;  // 4194304 float4 tasks
    int t = blockIdx.x * 256 + threadIdx.x;
    if (t < NF4) {
        int pg = t >> 8;  // (t*4)/1024 : whole block maps to one point -> uniform branch
        bool k = g_keep[pg] != 0;
        float4 v = make_float4(0.f, 0.f, 0.f, 0.f);
        if (k) v = ((const float4*)features)[t];
        ((float4*)out)[12288 + t] = v;  // 49152/4 offset
    } else {
        int s = t - NF4;
        if (s < NB * NP * 3) {
            int pg = s / 3;
            out[s] = g_keep[pg] ? centers[s] : 0.0f;
        } else {
            int e = s - NB * NP * 3;
            int pg = e / 3;
            out[16826368 + e] = g_keep[pg] ? cls[e] : 0.0f;
        }
    }
}

extern "C" void kernel_launch(void* const* d_in, const int* in_sizes, int n_in,
                              void* d_out, int out_size)
{
    const float* centers  = (const float*)d_in[0];
    const float* features = (const float*)d_in[1];
    const float* cls      = (const float*)d_in[2];
    const float* radius   = (const float*)d_in[3];
    float* out = (float*)d_out;

    k1_sort<<<NB, 1024>>>(centers, cls, radius);
    k2_mask<<<dim3(16, NB), 128>>>();
    k3_scan<<<NB, 32>>>(out + 16875520);
    const int total = NB * NP * NCF / 4 + 2 * NB * NP * 3;  // 4292608
    k4_apply<<<total / 256, 256>>>(centers, features, cls, out);
}

// round 3
// speedup vs baseline: 2.1695x; 2.1695x over previous
#include <cuda_runtime.h>
#include <cstdint>

#define NB 8
#define NP 2048
#define NCF 1024
#define NCLS 3

// ---------------- scratch (__device__ globals; no allocation allowed) ----------------
__device__ float4 g_pt[NB][NP];                    // sorted (x,y,z,label-bits)
__device__ float  g_L[NB][NP];                     // exact squared-radius threshold
__device__ int    g_sidx[NB][NP];                  // sorted -> original index
__device__ unsigned long long g_mask[NB][NP][32];  // suppression bitmask rows (4MB)
__device__ unsigned char g_keep[NB * NP];          // keep flags by original index

// ---------------- K1: scores, labels, sort by (score desc, idx asc) ----------------
__global__ __launch_bounds__(1024) void k1_sort(const float* __restrict__ centers,
                                                const float* __restrict__ cls,
                                                const float* __restrict__ radius)
{
    __shared__ unsigned long long keys[NP];
    const int b = blockIdx.x;
    const int tid = threadIdx.x;

    for (int p = tid; p < NP; p += 1024) {
        const float* cp = cls + ((size_t)b * NP + p) * NCLS;
        float c0 = cp[0], c1 = cp[1], c2 = cp[2];
        float s = c0;
        if (c1 > s) s = c1;
        if (c2 > s) s = c2;
        unsigned su = __float_as_uint(s);
        unsigned ord = su ^ ((su & 0x80000000u) ? 0xFFFFFFFFu : 0x80000000u);
        // ascending sort of key => score descending, index ascending (argmax tie-break)
        keys[p] = ((unsigned long long)(~ord) << 32) | (unsigned)p;
    }
    __syncthreads();

    // bitonic sort, 2048 elems, 1024 threads
    for (int k = 2; k <= NP; k <<= 1) {
        for (int j = k >> 1; j > 0; j >>= 1) {
            for (int t = tid; t < NP; t += 1024) {
                int ixj = t ^ j;
                if (ixj > t) {
                    unsigned long long a = keys[t], c = keys[ixj];
                    bool up = ((t & k) == 0);
                    if ((a > c) == up) { keys[t] = c; keys[ixj] = a; }
                }
            }
            __syncthreads();
        }
    }

    for (int p = tid; p < NP; p += 1024) {
        int idx = (int)(keys[p] & 0xFFFFFFFFu);
        g_sidx[b][p] = idx;
        const float* cc = centers + ((size_t)b * NP + idx) * 3;
        const float* cp = cls + ((size_t)b * NP + idx) * NCLS;
        float c0 = cp[0], c1 = cp[1], c2 = cp[2];
        int lab = 0; float s = c0;
        if (c1 > s) { s = c1; lab = 1; }
        if (c2 > s) { s = c2; lab = 2; }
        g_pt[b][p] = make_float4(cc[0], cc[1], cc[2], __int_as_float(lab));

        // Exact threshold: RN(sqrt(d2)) < r  <=>  d2 <= L, where
        // L = largest f32 strictly below M = ((pred(r)+r)/2)^2 (real arithmetic).
        float r = radius[lab];
        float L;
        if (!(r > 0.0f)) {
            L = -1.0f;  // dist < r never true
        } else {
            float pr = __uint_as_float(__float_as_uint(r) - 1u);
            double m = 0.5 * ((double)pr + (double)r);
            double M = m * m;
            float f = (float)M;
            if ((double)f < M) L = f;
            else L = __uint_as_float(__float_as_uint(f) - 1u);
        }
        g_L[b][p] = L;
    }
}

// ---------------- K2: build suppression bit-matrix in sorted order ----------------
// grid (16, 8): 16 row-tiles of 128 rows per scene. 128 threads = 4 warps,
// one warp owns 32 consecutive rows (lane = row). Broadcast j-data from shared.
__global__ __launch_bounds__(128) void k2_mask()
{
    __shared__ float4 spt[NP];  // 32KB
    const int b = blockIdx.y;
    const int tid = threadIdx.x;

    for (int k = tid; k < NP; k += 128) spt[k] = g_pt[b][k];
    __syncthreads();

    const int warp = tid >> 5, lane = tid & 31;
    const int wbase = blockIdx.x * 128 + warp * 32;
    const int i = wbase + lane;

    const float4 me = spt[i];
    const int li = __float_as_int(me.w);
    const float Li = g_L[b][i];

    for (int jc = 0; jc < 32; jc++) {
        if (jc * 64 + 63 < wbase) continue;  // all j < i in this word: never read by scan
        unsigned long long bits = 0ull;
        const int jb = jc << 6;
        #pragma unroll 8
        for (int jj = 0; jj < 64; jj++) {
            float4 q = spt[jb + jj];
            float dx = me.x - q.x;
            float dy = me.y - q.y;
            float dz = me.z - q.z;
            // match XLA: (dx*dx + dy*dy) + dz*dz, no FMA contraction
            float d2 = __fadd_rn(__fadd_rn(__fmul_rn(dx, dx), __fmul_rn(dy, dy)),
                                 __fmul_rn(dz, dz));
            bool pr = (__float_as_int(q.w) == li) && (d2 <= Li);
            bits |= ((unsigned long long)pr) << jj;
        }
        g_mask[b][i][jc] = bits;
    }
}

// ---------------- K3: chunked greedy scan, one 128-thread block per scene ----------------
// Chunk = 64 rows. Thread 0 resolves the 64x64 diagonal block serially in registers;
// all 128 threads then OR kept rows into the removed vector in parallel.
// Next chunk's 16KB of rows is double-buffered via cp.async.
__global__ __launch_bounds__(128) void k3_scan(float* __restrict__ out_keep)
{
    __shared__ unsigned long long buf[2][64][32];   // 32KB double buffer
    __shared__ unsigned long long srem[32];          // removed bits (2048)
    __shared__ unsigned long long part[4][32];       // per-rowgroup partial ORs
    __shared__ unsigned long long s_keep;            // chunk keep bits broadcast
    __shared__ int ssidx[NP];                        // 8KB

    const int b = blockIdx.x;
    const int tid = threadIdx.x;

    for (int k = tid; k < NP; k += 128) ssidx[k] = g_sidx[b][k];
    if (tid < 32) srem[tid] = 0ull;

    // prefetch chunk 0
    {
        const float4* src = (const float4*)&g_mask[b][0][0];
        float4* dst = (float4*)&buf[0][0][0];
        #pragma unroll
        for (int v = tid; v < 1024; v += 128) {
            unsigned sa = (unsigned)__cvta_generic_to_shared(dst + v);
            asm volatile("cp.async.cg.shared.global [%0], [%1], 16;\n"
                         :: "r"(sa), "l"(src + v) : "memory");
        }
        asm volatile("cp.async.commit_group;\n" ::: "memory");
    }

    for (int c = 0; c < 32; c++) {
        const int cb = c & 1;

        // issue prefetch of chunk c+1 into the other buffer
        if (c < 31) {
            const float4* src = (const float4*)&g_mask[b][(c + 1) * 64][0];
            float4* dst = (float4*)&buf[cb ^ 1][0][0];
            #pragma unroll
            for (int v = tid; v < 1024; v += 128) {
                unsigned sa = (unsigned)__cvta_generic_to_shared(dst + v);
                asm volatile("cp.async.cg.shared.global [%0], [%1], 16;\n"
                             :: "r"(sa), "l"(src + v) : "memory");
            }
            asm volatile("cp.async.commit_group;\n" ::: "memory");
            asm volatile("cp.async.wait_group 1;\n" ::: "memory");
        } else {
            asm volatile("cp.async.wait_group 0;\n" ::: "memory");
        }
        __syncthreads();  // chunk c resident; srem from previous chunk final

        // --- serial diagonal resolution (thread 0, pure registers) ---
        if (tid == 0) {
            unsigned Dlo[64], Dhi[64];
            #pragma unroll
            for (int r = 0; r < 64; r++) {
                unsigned long long d = buf[cb][r][c];
                Dlo[r] = (unsigned)d;
                Dhi[r] = (unsigned)(d >> 32);
            }
            unsigned long long rm = srem[c];
            unsigned lo = ~(unsigned)rm;
            unsigned hi = ~(unsigned)(rm >> 32);
            unsigned klo = 0, khi = 0;
            #pragma unroll
            for (int r = 0; r < 32; r++) {
                unsigned s = (unsigned)((int)(lo << (31 - r)) >> 31);  // all-ones if row r alive
                klo |= s & (1u << r);
                lo &= ~(Dlo[r] & s);
                hi &= ~(Dhi[r] & s);
            }
            #pragma unroll
            for (int r = 0; r < 32; r++) {
                unsigned s = (unsigned)((int)(hi << (31 - r)) >> 31);
                khi |= s & (1u << r);
                hi &= ~(Dhi[32 + r] & s);
            }
            s_keep = ((unsigned long long)khi << 32) | klo;
        }
        __syncthreads();

        const unsigned long long keep = s_keep;

        // write keep outputs for this chunk (off critical path)
        if (tid < 64) {
            int row = c * 64 + tid;
            int oi = ssidx[row];
            unsigned bit = (unsigned)((keep >> tid) & 1ull);
            g_keep[b * NP + oi] = (unsigned char)bit;
            out_keep[b * NP + oi] = bit ? 1.0f : 0.0f;
        }

        // --- batch OR of kept rows into removed vector ---
        {
            const int rg = tid >> 5;      // row group 0..3 (16 rows each)
            const int w = tid & 31;       // word 0..31
            unsigned long long p = 0ull;
            #pragma unroll
            for (int k = 0; k < 16; k++) {
                int r = rg * 16 + k;
                unsigned long long m = (unsigned long long)(-(long long)((keep >> r) & 1ull));
                p |= buf[cb][r][w] & m;
            }
            part[rg][w] = p;
        }
        __syncthreads();
        if (tid < 32)
            srem[tid] |= part[0][tid] | part[1][tid] | part[2][tid] | part[3][tid];
        __syncthreads();  // protects buf[cb] reuse by prefetch and srem for next chunk
    }
}

// ---------------- K4: apply keep mask to all output sections ----------------
// out layout (floats): centers @0 (49152) | features @49152 (16777216) |
//                      cls @16826368 (49152) | keep @16875520 (16384, written by K3)
__global__ __launch_bounds__(256) void k4_apply(const float* __restrict__ centers,
                                                const float* __restrict__ features,
                                                const float* __restrict__ cls,
                                                float* __restrict__ out)
{
    const int NF4 = NB * NP * NCF / 4;  // 4194304 float4 tasks
    int t = blockIdx.x * 256 + threadIdx.x;
    if (t < NF4) {
        int pg = t >> 8;  // (t*4)/1024 : whole block maps to one point -> uniform branch
        bool k = g_keep[pg] != 0;
        float4 v = make_float4(0.f, 0.f, 0.f, 0.f);
        if (k) v = ((const float4*)features)[t];
        ((float4*)out)[12288 + t] = v;  // 49152/4 offset
    } else {
        int s = t - NF4;
        if (s < NB * NP * 3) {
            int pg = s / 3;
            out[s] = g_keep[pg] ? centers[s] : 0.0f;
        } else {
            int e = s - NB * NP * 3;
            int pg = e / 3;
            out[16826368 + e] = g_keep[pg] ? cls[e] : 0.0f;
        }
    }
}

extern "C" void kernel_launch(void* const* d_in, const int* in_sizes, int n_in,
                              void* d_out, int out_size)
{
    const float* centers  = (const float*)d_in[0];
    const float* features = (const float*)d_in[1];
    const float* cls      = (const float*)d_in[2];
    const float* radius   = (const float*)d_in[3];
    float* out = (float*)d_out;

    k1_sort<<<NB, 1024>>>(centers, cls, radius);
    k2_mask<<<dim3(16, NB), 128>>>();
    k3_scan<<<NB, 128>>>(out + 16875520);
    const int total = NB * NP * NCF / 4 + 2 * NB * NP * 3;  // 4292608
    k4_apply<<<total / 256, 256>>>(centers, features, cls, out);
}

// round 5
// speedup vs baseline: 2.5616x; 1.1807x over previous
#include <cuda_runtime.h>
#include <cstdint>

#define NB 8
#define NP 2048
#define NCF 1024
#define NCLS 3

// ---------------- scratch (__device__ globals; no allocation allowed) ----------------
__device__ float4 g_xy[NB][NP / 2];                // sorted SoA pairs {x0,x1,y0,y1}
__device__ float2 g_z[NB][NP / 2];                 // sorted SoA pairs {z0,z1}
__device__ int    g_lab[NB][NP];                   // sorted labels
__device__ float  g_L[NB][NP];                     // exact squared-radius threshold
__device__ int    g_sidx[NB][NP];                  // sorted -> original index
__device__ unsigned long long g_mask[NB][NP][32];  // suppression bitmask rows (4MB)
__device__ unsigned char g_keep[NB * NP];          // keep flags by original index

// packed f32x2 helpers (two independent RN ops -> bit-identical to scalar RN)
__device__ __forceinline__ unsigned long long f2add(unsigned long long a, unsigned long long b) {
    unsigned long long r;
    asm("add.rn.f32x2 %0, %1, %2;" : "=l"(r) : "l"(a), "l"(b));
    return r;
}
__device__ __forceinline__ unsigned long long f2mul(unsigned long long a, unsigned long long b) {
    unsigned long long r;
    asm("mul.rn.f32x2 %0, %1, %2;" : "=l"(r) : "l"(a), "l"(b));
    return r;
}
__device__ __forceinline__ unsigned long long pk2(float a, float b) {
    unsigned long long r;
    asm("mov.b64 %0, {%1, %2};" : "=l"(r) : "f"(a), "f"(b));
    return r;
}

// ---------------- K1: rank-by-counting sort (score desc, idx asc) ----------------
// grid (64, 8), 256 threads. Each block computes all 2048 keys of its scene in
// shared, then each warp ranks 4 points; lane<4 scatters the sorted SoA entry.
__global__ __launch_bounds__(256) void k1_rank(const float* __restrict__ centers,
                                               const float* __restrict__ cls,
                                               const float* __restrict__ radius)
{
    __shared__ unsigned long long keys[NP];  // 16KB
    const int b = blockIdx.y;
    const int tid = threadIdx.x;

    for (int p = tid; p < NP; p += 256) {
        const float* cp = cls + ((size_t)b * NP + p) * NCLS;
        float c0 = cp[0], c1 = cp[1], c2 = cp[2];
        float s = c0;
        if (c1 > s) s = c1;
        if (c2 > s) s = c2;
        unsigned su = __float_as_uint(s);
        unsigned ord = su ^ ((su & 0x80000000u) ? 0xFFFFFFFFu : 0x80000000u);
        // ascending key order => score descending, index ascending (argmax tie-break)
        keys[p] = ((unsigned long long)(~ord) << 32) | (unsigned)p;
    }
    __syncthreads();

    const int warp = tid >> 5, lane = tid & 31;
    const int pbase = blockIdx.x * 32 + warp * 4;

    const unsigned long long k0 = keys[pbase + 0];
    const unsigned long long k1 = keys[pbase + 1];
    const unsigned long long k2 = keys[pbase + 2];
    const unsigned long long k3 = keys[pbase + 3];
    int r0 = 0, r1 = 0, r2 = 0, r3 = 0;
    #pragma unroll 4
    for (int j = lane; j < NP; j += 32) {
        unsigned long long kj = keys[j];
        r0 += (kj < k0);
        r1 += (kj < k1);
        r2 += (kj < k2);
        r3 += (kj < k3);
    }
    r0 = __reduce_add_sync(0xFFFFFFFFu, r0);
    r1 = __reduce_add_sync(0xFFFFFFFFu, r1);
    r2 = __reduce_add_sync(0xFFFFFFFFu, r2);
    r3 = __reduce_add_sync(0xFFFFFFFFu, r3);

    if (lane < 4) {
        int p = pbase + lane;
        int rank = (lane == 0) ? r0 : (lane == 1) ? r1 : (lane == 2) ? r2 : r3;

        const float* cp = cls + ((size_t)b * NP + p) * NCLS;
        float c0 = cp[0], c1 = cp[1], c2 = cp[2];
        int lab = 0; float s = c0;
        if (c1 > s) { s = c1; lab = 1; }
        if (c2 > s) { s = c2; lab = 2; }

        const float* cc = centers + ((size_t)b * NP + p) * 3;
        float x = cc[0], y = cc[1], z = cc[2];

        // Exact threshold: RN(sqrt(d2)) < r  <=>  d2 <= L, where
        // L = largest f32 strictly below M = ((pred(r)+r)/2)^2 (real arithmetic).
        float r = radius[lab];
        float L;
        if (!(r > 0.0f)) {
            L = -1.0f;
        } else {
            float pr = __uint_as_float(__float_as_uint(r) - 1u);
            double m = 0.5 * ((double)pr + (double)r);
            double M = m * m;
            float f = (float)M;
            if ((double)f < M) L = f;
            else L = __uint_as_float(__float_as_uint(f) - 1u);
        }

        int pr2 = rank >> 1, c = rank & 1;
        float* xy = (float*)&g_xy[b][0];
        xy[pr2 * 4 + c] = x;
        xy[pr2 * 4 + 2 + c] = y;
        ((float*)&g_z[b][0])[pr2 * 2 + c] = z;
        g_lab[b][rank] = lab;
        g_L[b][rank] = L;
        g_sidx[b][rank] = p;
    }
}

// ---------------- K2: build suppression bit-matrix (packed f32x2) ----------------
// grid (16, 8): 16 row-tiles of 128 rows per scene. Each warp owns 32 rows
// (lane = row). Per-scene class bitmasks replace the per-pair label test.
__global__ __launch_bounds__(128) void k2_mask()
{
    __shared__ ulonglong2 sxy[NP / 2];          // 16KB {xpair, ypair}
    __shared__ unsigned long long szp[NP / 2];  // 8KB  {zpair}
    __shared__ int slab[NP];                    // 8KB
    __shared__ unsigned long long cbits[3][32]; // class membership bitmasks

    const int b = blockIdx.y;
    const int tid = threadIdx.x;

    for (int k = tid; k < NP / 2; k += 128) {
        sxy[k] = ((const ulonglong2*)&g_xy[b][0])[k];
        szp[k] = ((const unsigned long long*)&g_z[b][0])[k];
    }
    for (int k = tid; k < NP; k += 128) slab[k] = g_lab[b][k];
    __syncthreads();

    if (tid < 96) {
        int c = tid >> 5, w = tid & 31;
        unsigned long long m = 0ull;
        #pragma unroll 8
        for (int jj = 0; jj < 64; jj++)
            m |= (unsigned long long)(slab[w * 64 + jj] == c) << jj;
        cbits[c][w] = m;
    }
    __syncthreads();

    const int warp = tid >> 5, lane = tid & 31;
    const int wbase = blockIdx.x * 128 + warp * 32;
    const int i = wbase + lane;

    const float xi = ((const float*)&sxy[0])[(i >> 1) * 4 + (i & 1)];
    const float yi = ((const float*)&sxy[0])[(i >> 1) * 4 + 2 + (i & 1)];
    const float zi = ((const float*)&szp[0])[(i >> 1) * 2 + (i & 1)];
    const int li = slab[i];
    const float Li = g_L[b][i];

    const unsigned long long nmx = pk2(-xi, -xi);
    const unsigned long long nmy = pk2(-yi, -yi);
    const unsigned long long nmz = pk2(-zi, -zi);
    const unsigned long long Lp  = pk2(Li, Li);

    for (int jc = 0; jc < 32; jc++) {
        if (jc * 64 + 63 < wbase) continue;  // all j < i in this word: never read by scan
        unsigned long long bits = 0ull;
        const int jb = jc * 32;
        #pragma unroll 8
        for (int q = 0; q < 32; q++) {
            ulonglong2 v = sxy[jb + q];
            unsigned long long zp = szp[jb + q];
            // dq = q - me (negated diff; squares identical to reference)
            unsigned long long dx = f2add(v.x, nmx);
            unsigned long long dy = f2add(v.y, nmy);
            unsigned long long dz = f2add(zp, nmz);
            unsigned long long x2 = f2mul(dx, dx);
            unsigned long long y2 = f2mul(dy, dy);
            unsigned long long z2 = f2mul(dz, dz);
            // match XLA: (dx*dx + dy*dy) + dz*dz
            unsigned long long d2 = f2add(f2add(x2, y2), z2);
            // t = Li - d2; suppress iff sign(t)==0  (<=> d2 <= Li exactly)
            unsigned long long t = f2add(Lp, d2 ^ 0x8000000080000000ull);
            unsigned tlo = (unsigned)t;
            unsigned thi = (unsigned)(t >> 32);
            bits |= (unsigned long long)((~tlo) >> 31) << (2 * q);
            bits |= (unsigned long long)((~thi) >> 31) << (2 * q + 1);
        }
        g_mask[b][i][jc] = bits & cbits[li][jc];
    }
}

// ---------------- K3: chunked greedy scan, one 256-thread block per scene ----------------
__global__ __launch_bounds__(256) void k3_scan(float* __restrict__ out_keep)
{
    __shared__ unsigned long long buf[2][64][32];   // 32KB double buffer
    __shared__ unsigned long long srem[32];          // removed bits (2048)
    __shared__ unsigned long long part[8][32];       // per-rowgroup partial ORs
    __shared__ unsigned long long s_keep;            // chunk keep bits broadcast
    __shared__ int ssidx[NP];                        // 8KB

    const int b = blockIdx.x;
    const int tid = threadIdx.x;

    for (int k = tid; k < NP; k += 256) ssidx[k] = g_sidx[b][k];
    if (tid < 32) srem[tid] = 0ull;

    // prefetch chunk 0
    {
        const float4* src = (const float4*)&g_mask[b][0][0];
        float4* dst = (float4*)&buf[0][0][0];
        #pragma unroll
        for (int v = tid; v < 1024; v += 256) {
            unsigned sa = (unsigned)__cvta_generic_to_shared(dst + v);
            asm volatile("cp.async.cg.shared.global [%0], [%1], 16;\n"
                         :: "r"(sa), "l"(src + v) : "memory");
        }
        asm volatile("cp.async.commit_group;\n" ::: "memory");
    }

    for (int c = 0; c < 32; c++) {
        const int cb = c & 1;

        if (c < 31) {
            const float4* src = (const float4*)&g_mask[b][(c + 1) * 64][0];
            float4* dst = (float4*)&buf[cb ^ 1][0][0];
            #pragma unroll
            for (int v = tid; v < 1024; v += 256) {
                unsigned sa = (unsigned)__cvta_generic_to_shared(dst + v);
                asm volatile("cp.async.cg.shared.global [%0], [%1], 16;\n"
                             :: "r"(sa), "l"(src + v) : "memory");
            }
            asm volatile("cp.async.commit_group;\n" ::: "memory");
            asm volatile("cp.async.wait_group 1;\n" ::: "memory");
        } else {
            asm volatile("cp.async.wait_group 0;\n" ::: "memory");
        }
        __syncthreads();  // chunk c resident; srem final

        // --- serial diagonal resolution (thread 0, pure registers) ---
        if (tid == 0) {
            unsigned Dlo[64], Dhi[64];
            #pragma unroll
            for (int r = 0; r < 64; r++) {
                unsigned long long d = buf[cb][r][c];
                Dlo[r] = (unsigned)d;
                Dhi[r] = (unsigned)(d >> 32);
            }
            unsigned long long rm = srem[c];
            unsigned lo = ~(unsigned)rm;
            unsigned hi = ~(unsigned)(rm >> 32);
            unsigned klo = 0, khi = 0;
            #pragma unroll
            for (int r = 0; r < 32; r++) {
                unsigned s = (unsigned)((int)(lo << (31 - r)) >> 31);
                klo |= s & (1u << r);
                lo &= ~(Dlo[r] & s);
                hi &= ~(Dhi[r] & s);
            }
            #pragma unroll
            for (int r = 0; r < 32; r++) {
                unsigned s = (unsigned)((int)(hi << (31 - r)) >> 31);
                khi |= s & (1u << r);
                hi &= ~(Dhi[32 + r] & s);
            }
            s_keep = ((unsigned long long)khi << 32) | klo;
        }
        __syncthreads();

        const unsigned long long keep = s_keep;

        if (tid < 64) {
            int row = c * 64 + tid;
            int oi = ssidx[row];
            unsigned bit = (unsigned)((keep >> tid) & 1ull);
            g_keep[b * NP + oi] = (unsigned char)bit;
            out_keep[b * NP + oi] = bit ? 1.0f : 0.0f;
        }

        // --- batch OR of kept rows into removed vector ---
        {
            const int rg = tid >> 5;      // row group 0..7 (8 rows each)
            const int w = tid & 31;       // word 0..31
            unsigned long long p = 0ull;
            #pragma unroll
            for (int k = 0; k < 8; k++) {
                int r = rg * 8 + k;
                unsigned long long m = (unsigned long long)(-(long long)((keep >> r) & 1ull));
                p |= buf[cb][r][w] & m;
            }
            part[rg][w] = p;
        }
        __syncthreads();
        if (tid < 32)
            srem[tid] |= (part[0][tid] | part[1][tid]) | (part[2][tid] | part[3][tid]) |
                         (part[4][tid] | part[5][tid]) | (part[6][tid] | part[7][tid]);
        __syncthreads();  // protects buf[cb] reuse by prefetch and srem for next chunk
    }
}

// ---------------- K4: apply keep mask to all output sections ----------------
// out layout (floats): centers @0 (49152) | features @49152 (16777216) |
//                      cls @16826368 (49152) | keep @16875520 (16384, written by K3)
__global__ __launch_bounds__(256) void k4_apply(const float* __restrict__ centers,
                                                const float* __restrict__ features,
                                                const float* __restrict__ cls,
                                                float* __restrict__ out)
{
    const int NF4 = NB * NP * NCF / 4;  // 4194304 float4 tasks
    int t = blockIdx.x * 256 + threadIdx.x;
    if (t < NF4) {
        int pg = t >> 8;  // whole 256-thread block maps to one point -> uniform branch
        bool k = g_keep[pg] != 0;
        float4 v = make_float4(0.f, 0.f, 0.f, 0.f);
        if (k) v = __ldcs(((const float4*)features) + t);
        __stcs(((float4*)out) + 12288 + t, v);  // 49152/4 offset
    } else {
        int s = t - NF4;
        if (s < NB * NP * 3) {
            int pg = s / 3;
            out[s] = g_keep[pg] ? centers[s] : 0.0f;
        } else {
            int e = s - NB * NP * 3;
            int pg = e / 3;
            out[16826368 + e] = g_keep[pg] ? cls[e] : 0.0f;
        }
    }
}

extern "C" void kernel_launch(void* const* d_in, const int* in_sizes, int n_in,
                              void* d_out, int out_size)
{
    const float* centers  = (const float*)d_in[0];
    const float* features = (const float*)d_in[1];
    const float* cls      = (const float*)d_in[2];
    const float* radius   = (const float*)d_in[3];
    float* out = (float*)d_out;

    k1_rank<<<dim3(64, NB), 256>>>(centers, cls, radius);
    k2_mask<<<dim3(16, NB), 128>>>();
    k3_scan<<<NB, 256>>>(out + 16875520);
    const int total = NB * NP * NCF / 4 + 2 * NB * NP * 3;  // 4292608
    k4_apply<<<total / 256, 256>>>(centers, features, cls, out);
}

// round 6
// speedup vs baseline: 2.9051x; 1.1341x over previous
#include <cuda_runtime.h>
#include <cstdint>

#define NB 8
#define NP 2048
#define NCF 1024
#define NCLS 3

// ---------------- scratch (__device__ globals; no allocation allowed) ----------------
__device__ float4 g_xy[NB][NP / 2];                // sorted SoA pairs {x0,x1,y0,y1}
__device__ float2 g_z[NB][NP / 2];                 // sorted SoA pairs {z0,z1}
__device__ int    g_lab[NB][NP];                   // sorted labels
__device__ float  g_L[NB][NP];                     // exact squared-radius threshold
__device__ int    g_sidx[NB][NP];                  // sorted -> original index
__device__ unsigned long long g_mask[NB][NP][32];  // suppression bitmask rows (4MB)
__device__ unsigned char g_keep[NB * NP];          // keep flags by original index

// packed f32x2 helpers (two independent RN ops -> bit-identical to scalar RN)
__device__ __forceinline__ unsigned long long f2add(unsigned long long a, unsigned long long b) {
    unsigned long long r;
    asm("add.rn.f32x2 %0, %1, %2;" : "=l"(r) : "l"(a), "l"(b));
    return r;
}
__device__ __forceinline__ unsigned long long f2mul(unsigned long long a, unsigned long long b) {
    unsigned long long r;
    asm("mul.rn.f32x2 %0, %1, %2;" : "=l"(r) : "l"(a), "l"(b));
    return r;
}
__device__ __forceinline__ unsigned long long pk2(float a, float b) {
    unsigned long long r;
    asm("mov.b64 %0, {%1, %2};" : "=l"(r) : "f"(a), "f"(b));
    return r;
}

// ---------------- K1: rank-by-counting sort (score desc, idx asc) ----------------
__global__ __launch_bounds__(256) void k1_rank(const float* __restrict__ centers,
                                               const float* __restrict__ cls,
                                               const float* __restrict__ radius)
{
    __shared__ unsigned long long keys[NP];  // 16KB
    const int b = blockIdx.y;
    const int tid = threadIdx.x;

    for (int p = tid; p < NP; p += 256) {
        const float* cp = cls + ((size_t)b * NP + p) * NCLS;
        float c0 = cp[0], c1 = cp[1], c2 = cp[2];
        float s = c0;
        if (c1 > s) s = c1;
        if (c2 > s) s = c2;
        unsigned su = __float_as_uint(s);
        unsigned ord = su ^ ((su & 0x80000000u) ? 0xFFFFFFFFu : 0x80000000u);
        // ascending key order => score descending, index ascending (argmax tie-break)
        keys[p] = ((unsigned long long)(~ord) << 32) | (unsigned)p;
    }
    __syncthreads();

    const int warp = tid >> 5, lane = tid & 31;
    const int pbase = blockIdx.x * 32 + warp * 4;

    const unsigned long long k0 = keys[pbase + 0];
    const unsigned long long k1 = keys[pbase + 1];
    const unsigned long long k2 = keys[pbase + 2];
    const unsigned long long k3 = keys[pbase + 3];
    int r0 = 0, r1 = 0, r2 = 0, r3 = 0;
    #pragma unroll 4
    for (int j = lane; j < NP; j += 32) {
        unsigned long long kj = keys[j];
        r0 += (kj < k0);
        r1 += (kj < k1);
        r2 += (kj < k2);
        r3 += (kj < k3);
    }
    r0 = __reduce_add_sync(0xFFFFFFFFu, r0);
    r1 = __reduce_add_sync(0xFFFFFFFFu, r1);
    r2 = __reduce_add_sync(0xFFFFFFFFu, r2);
    r3 = __reduce_add_sync(0xFFFFFFFFu, r3);

    if (lane < 4) {
        int p = pbase + lane;
        int rank = (lane == 0) ? r0 : (lane == 1) ? r1 : (lane == 2) ? r2 : r3;

        const float* cp = cls + ((size_t)b * NP + p) * NCLS;
        float c0 = cp[0], c1 = cp[1], c2 = cp[2];
        int lab = 0; float s = c0;
        if (c1 > s) { s = c1; lab = 1; }
        if (c2 > s) { s = c2; lab = 2; }

        const float* cc = centers + ((size_t)b * NP + p) * 3;
        float x = cc[0], y = cc[1], z = cc[2];

        // Exact threshold: RN(sqrt(d2)) < r  <=>  d2 <= L, where
        // L = largest f32 strictly below M = ((pred(r)+r)/2)^2 (real arithmetic).
        float r = radius[lab];
        float L;
        if (!(r > 0.0f)) {
            L = -1.0f;
        } else {
            float pr = __uint_as_float(__float_as_uint(r) - 1u);
            double m = 0.5 * ((double)pr + (double)r);
            double M = m * m;
            float f = (float)M;
            if ((double)f < M) L = f;
            else L = __uint_as_float(__float_as_uint(f) - 1u);
        }

        int pr2 = rank >> 1, c = rank & 1;
        float* xy = (float*)&g_xy[b][0];
        xy[pr2 * 4 + c] = x;
        xy[pr2 * 4 + 2 + c] = y;
        ((float*)&g_z[b][0])[pr2 * 2 + c] = z;
        g_lab[b][rank] = lab;
        g_L[b][rank] = L;
        g_sidx[b][rank] = p;
    }
}

// ---------------- K2: build suppression bit-matrix (packed f32x2) ----------------
// grid (16, 8), 256 threads: warps 0-3 own 32 rows each (lane = row) and do EVEN
// jc words; warps 4-7 mirror the same rows for ODD jc words -> 2 warps/SMSP.
__global__ __launch_bounds__(256) void k2_mask()
{
    __shared__ ulonglong2 sxy[NP / 2];          // 16KB {xpair, ypair}
    __shared__ unsigned long long szp[NP / 2];  // 8KB  {zpair}
    __shared__ int slab[NP];                    // 8KB
    __shared__ unsigned long long cbits[3][32]; // class membership bitmasks

    const int b = blockIdx.y;
    const int tid = threadIdx.x;

    for (int k = tid; k < NP / 2; k += 256) {
        sxy[k] = ((const ulonglong2*)&g_xy[b][0])[k];
        szp[k] = ((const unsigned long long*)&g_z[b][0])[k];
    }
    for (int k = tid; k < NP; k += 256) slab[k] = g_lab[b][k];
    __syncthreads();

    if (tid < 96) {
        int c = tid >> 5, w = tid & 31;
        unsigned long long m = 0ull;
        #pragma unroll 8
        for (int jj = 0; jj < 64; jj++)
            m |= (unsigned long long)(slab[w * 64 + jj] == c) << jj;
        cbits[c][w] = m;
    }
    __syncthreads();

    const int warp = tid >> 5, lane = tid & 31;
    const int sub = warp & 3, half = warp >> 2;
    const int wbase = blockIdx.x * 128 + sub * 32;
    const int i = wbase + lane;

    const float xi = ((const float*)&sxy[0])[(i >> 1) * 4 + (i & 1)];
    const float yi = ((const float*)&sxy[0])[(i >> 1) * 4 + 2 + (i & 1)];
    const float zi = ((const float*)&szp[0])[(i >> 1) * 2 + (i & 1)];
    const int li = slab[i];
    const float Li = g_L[b][i];

    const unsigned long long nmx = pk2(-xi, -xi);
    const unsigned long long nmy = pk2(-yi, -yi);
    const unsigned long long nmz = pk2(-zi, -zi);
    const unsigned long long Lp  = pk2(Li, Li);

    for (int jc = half; jc < 32; jc += 2) {
        if (jc * 64 + 63 < wbase) continue;  // all j < i in this word: never read by scan
        unsigned long long bits = 0ull;
        const int jb = jc * 32;
        #pragma unroll 8
        for (int q = 0; q < 32; q++) {
            ulonglong2 v = sxy[jb + q];
            unsigned long long zp = szp[jb + q];
            // dq = q - me (negated diff; squares identical to reference)
            unsigned long long dx = f2add(v.x, nmx);
            unsigned long long dy = f2add(v.y, nmy);
            unsigned long long dz = f2add(zp, nmz);
            unsigned long long x2 = f2mul(dx, dx);
            unsigned long long y2 = f2mul(dy, dy);
            unsigned long long z2 = f2mul(dz, dz);
            // match XLA: (dx*dx + dy*dy) + dz*dz
            unsigned long long d2 = f2add(f2add(x2, y2), z2);
            // t = Li - d2; suppress iff sign(t)==0  (<=> d2 <= Li exactly)
            unsigned long long t = f2add(Lp, d2 ^ 0x8000000080000000ull);
            unsigned tlo = (unsigned)t;
            unsigned thi = (unsigned)(t >> 32);
            bits |= (unsigned long long)((~tlo) >> 31) << (2 * q);
            bits |= (unsigned long long)((~thi) >> 31) << (2 * q + 1);
        }
        g_mask[b][i][jc] = bits & cbits[li][jc];
    }
}

// ---------------- K3: warp-specialized pipelined greedy scan ----------------
// One 256-thread block per scene. Per iteration c:
//   warp 0: forward-word (chunk c-1 contribution to removed word c) + serial
//           64x64 diagonal for chunk c -> publishes skeep[c&1]
//   warps 1-7: OR chunk c-1's kept rows into srem (all 32 words), keep outputs
// 4-slot ring, prefetch 2 ahead, ONE __syncthreads per iteration.
#define RSTRIDE 34  // u64 per row (32 data + 2 pad): 272B, 16B-aligned rows
__global__ __launch_bounds__(256) void k3_scan(float* __restrict__ out_keep)
{
    __shared__ __align__(16) unsigned long long buf[4][64][RSTRIDE];  // ~68KB
    __shared__ unsigned long long srem[32];
    __shared__ unsigned long long part[7][32];
    __shared__ unsigned long long skeep[2];
    __shared__ int ssidx[NP];  // 8KB

    const int b = blockIdx.x;
    const int tid = threadIdx.x;
    const int warp = tid >> 5, lane = tid & 31;

    for (int k = tid; k < NP; k += 256) ssidx[k] = g_sidx[b][k];
    if (tid < 32) srem[tid] = 0ull;
    if (tid == 0) { skeep[0] = 0ull; skeep[1] = 0ull; }

    // prefetch chunks 0 and 1 (row-padded copy: 1024 float4 each)
    #pragma unroll
    for (int ch = 0; ch < 2; ch++) {
        const float4* src = (const float4*)&g_mask[b][ch * 64][0];
        for (int v = tid; v < 1024; v += 256) {
            int row = v >> 4, col = v & 15;
            float4* dst = (float4*)&buf[ch][row][0] + col;
            unsigned sa = (unsigned)__cvta_generic_to_shared(dst);
            asm volatile("cp.async.cg.shared.global [%0], [%1], 16;\n"
                         :: "r"(sa), "l"(src + v) : "memory");
        }
        asm volatile("cp.async.commit_group;\n" ::: "memory");
    }
    asm volatile("cp.async.wait_group 1;\n" ::: "memory");  // chunk 0 retired

    for (int c = 0; c < 32; c++) {
        __syncthreads();  // chunk c visible; prev OR & keep published; ring slot free

        // prefetch chunk c+2 into slot (c+2)&3 (slot's old data = chunk c-2, done)
        if (c < 30) {
            const float4* src = (const float4*)&g_mask[b][(c + 2) * 64][0];
            const int slot = (c + 2) & 3;
            for (int v = tid; v < 1024; v += 256) {
                int row = v >> 4, col = v & 15;
                float4* dst = (float4*)&buf[slot][row][0] + col;
                unsigned sa = (unsigned)__cvta_generic_to_shared(dst);
                asm volatile("cp.async.cg.shared.global [%0], [%1], 16;\n"
                             :: "r"(sa), "l"(src + v) : "memory");
            }
        }
        asm volatile("cp.async.commit_group;\n" ::: "memory");  // always (maybe empty)

        const int cur = c & 3, prv = (c + 3) & 3;
        const unsigned long long kprev = skeep[(c & 1) ^ 1];  // chunk c-1 keep (0 for c=0)

        if (warp == 0) {
            // forward word: chunk c-1 kept rows' contribution to removed word c
            unsigned long long m0 = (unsigned long long)(-(long long)((kprev >> lane) & 1ull));
            unsigned long long m1 = (unsigned long long)(-(long long)((kprev >> (lane + 32)) & 1ull));
            unsigned long long f = (buf[prv][lane][c] & m0) | (buf[prv][lane + 32][c] & m1);
            #pragma unroll
            for (int off = 16; off > 0; off >>= 1)
                f |= __shfl_xor_sync(0xFFFFFFFFu, f, off);

            if (lane == 0) {
                unsigned Dlo[32], Dhi[64];
                #pragma unroll
                for (int r = 0; r < 32; r++) {
                    unsigned long long d = buf[cur][r][c];
                    Dlo[r] = (unsigned)d;
                    Dhi[r] = (unsigned)(d >> 32);
                }
                #pragma unroll
                for (int r = 32; r < 64; r++)
                    Dhi[r] = (unsigned)(buf[cur][r][c] >> 32);

                unsigned long long rm = srem[c] | f;  // concurrent srem[c] update is benign:
                                                      // it only adds bits identical to f
                unsigned lo = ~(unsigned)rm;
                unsigned hi = ~(unsigned)(rm >> 32);
                unsigned klo = 0, khi = 0;
                #pragma unroll
                for (int r = 0; r < 32; r++) {
                    unsigned s = (unsigned)((int)(lo << (31 - r)) >> 31);
                    klo |= s & (1u << r);
                    lo &= ~(Dlo[r] & s);
                    hi &= ~(Dhi[r] & s);
                }
                #pragma unroll
                for (int r = 0; r < 32; r++) {
                    unsigned s = (unsigned)((int)(hi << (31 - r)) >> 31);
                    khi |= s & (1u << r);
                    hi &= ~(Dhi[32 + r] & s);
                }
                skeep[c & 1] = ((unsigned long long)khi << 32) | klo;
            }
        } else {
            // OR phase for chunk c-1 (kprev==0 at c==0 -> no-op content-wise)
            const int w = warp - 1;  // 0..6
            unsigned long long p = 0ull;
            for (int r = w; r < 64; r += 7) {
                unsigned long long m =
                    (unsigned long long)(-(long long)((kprev >> r) & 1ull));
                p |= buf[prv][r][lane] & m;
            }
            part[w][lane] = p;
            asm volatile("bar.sync 1, 224;" ::: "memory");
            if (warp == 1) {
                srem[lane] |= (part[0][lane] | part[1][lane]) |
                              (part[2][lane] | part[3][lane]) |
                              (part[4][lane] | part[5][lane]) | part[6][lane];
            }
            if (warp == 2 && c > 0) {
                int row = (c - 1) * 64 + lane;
                int oi = ssidx[row];
                unsigned bit = (unsigned)((kprev >> lane) & 1ull);
                g_keep[b * NP + oi] = (unsigned char)bit;
                out_keep[b * NP + oi] = bit ? 1.0f : 0.0f;
                int row2 = row + 32;
                int oi2 = ssidx[row2];
                unsigned bit2 = (unsigned)((kprev >> (lane + 32)) & 1ull);
                g_keep[b * NP + oi2] = (unsigned char)bit2;
                out_keep[b * NP + oi2] = bit2 ? 1.0f : 0.0f;
            }
        }
        asm volatile("cp.async.wait_group 1;\n" ::: "memory");  // retire chunk c+1's group
    }
    __syncthreads();
    if (tid < 64) {  // outputs for chunk 31 (skeep[31&1] = skeep[1])
        unsigned long long k31 = skeep[1];
        int row = 31 * 64 + tid;
        int oi = ssidx[row];
        unsigned bit = (unsigned)((k31 >> tid) & 1ull);
        g_keep[b * NP + oi] = (unsigned char)bit;
        out_keep[b * NP + oi] = bit ? 1.0f : 0.0f;
    }
}

// ---------------- K4: apply keep mask, 2 independent float4 per thread ----------------
// out layout (floats): centers @0 (49152) | features @49152 (16777216) |
//                      cls @16826368 (49152) | keep @16875520 (16384, written by K3)
__global__ __launch_bounds__(256) void k4_apply(const float* __restrict__ centers,
                                                const float* __restrict__ features,
                                                const float* __restrict__ cls,
                                                float* __restrict__ out)
{
    const int NF4h = NB * NP * NCF / 8;  // 2097152: half the float4 tasks
    int t = blockIdx.x * 256 + threadIdx.x;
    if (t < NF4h) {
        int t2 = t + NF4h;
        bool k1 = g_keep[t >> 8] != 0;    // block maps to one point -> uniform
        bool k2 = g_keep[t2 >> 8] != 0;
        float4 v1 = make_float4(0.f, 0.f, 0.f, 0.f);
        float4 v2 = make_float4(0.f, 0.f, 0.f, 0.f);
        if (k1) v1 = __ldcs(((const float4*)features) + t);
        if (k2) v2 = __ldcs(((const float4*)features) + t2);
        __stcs(((float4*)out) + 12288 + t, v1);   // 49152/4 offset
        __stcs(((float4*)out) + 12288 + t2, v2);
    } else {
        int s = t - NF4h;
        if (s < NB * NP * 3) {
            int pg = s / 3;
            out[s] = g_keep[pg] ? centers[s] : 0.0f;
        } else {
            int e = s - NB * NP * 3;
            int pg = e / 3;
            out[16826368 + e] = g_keep[pg] ? cls[e] : 0.0f;
        }
    }
}

extern "C" void kernel_launch(void* const* d_in, const int* in_sizes, int n_in,
                              void* d_out, int out_size)
{
    const float* centers  = (const float*)d_in[0];
    const float* features = (const float*)d_in[1];
    const float* cls      = (const float*)d_in[2];
    const float* radius   = (const float*)d_in[3];
    float* out = (float*)d_out;

    k1_rank<<<dim3(64, NB), 256>>>(centers, cls, radius);
    k2_mask<<<dim3(16, NB), 256>>>();
    k3_scan<<<NB, 256>>>(out + 16875520);
    const int total = NB * NP * NCF / 8 + 2 * NB * NP * 3;  // 2195456
    k4_apply<<<total / 256, 256>>>(centers, features, cls, out);
}